// round 7
// baseline (speedup 1.0000x reference)
#include <cuda_runtime.h>
#include <cuda_bf16.h>
#include <cuda_fp8.h>
#include <cstdint>

#define M_DIM 8192
#define N_DIM 2048
#define K_DIM 2048
#define KCH 16     // K / 128
#define NBLK 16    // N / 128

// ---------------- scratch (allocation-free: __device__ globals) ----------------
__device__ __align__(16) __nv_bfloat16 g_xq[(size_t)M_DIM * K_DIM];  // 32 MB
__device__ __align__(16) __nv_bfloat16 g_wq[(size_t)N_DIM * K_DIM];  //  8 MB
__device__ float g_sx[M_DIM * KCH];
__device__ float g_sw[NBLK * KCH];

// fp8 e4m3 round-trip (RN, satfinite) -> exact bf16
__device__ __forceinline__ __nv_bfloat16 fp8_rt(float v, float r) {
    __nv_fp8_e4m3 q(v * r);
    return __float2bfloat16(float(q));
}

// ---------------- quantize x: per (row, 128-chunk) scale ----------------
__global__ void quant_x_kernel(const float* __restrict__ x) {
    int wid = threadIdx.x >> 5, lane = threadIdx.x & 31;
    int id = blockIdx.x * 8 + wid;              // row-chunk id in [0, 8192*16)
    int row = id >> 4, c = id & 15;
    const float4* src = reinterpret_cast<const float4*>(x + (size_t)row * K_DIM + c * 128);
    float4 v = src[lane];
    float amax = fmaxf(fmaxf(fabsf(v.x), fabsf(v.y)), fmaxf(fabsf(v.z), fabsf(v.w)));
    #pragma unroll
    for (int o = 16; o > 0; o >>= 1) amax = fmaxf(amax, __shfl_xor_sync(0xffffffffu, amax, o));
    amax = fmaxf(amax, 1e-4f);
    float r = 448.0f / amax;
    __nv_bfloat162* dst =
        reinterpret_cast<__nv_bfloat162*>(g_xq + (size_t)row * K_DIM + c * 128 + lane * 4);
    __nv_bfloat162 p0, p1;
    p0.x = fp8_rt(v.x, r); p0.y = fp8_rt(v.y, r);
    p1.x = fp8_rt(v.z, r); p1.y = fp8_rt(v.w, r);
    dst[0] = p0; dst[1] = p1;
    if (lane == 0) g_sx[id] = amax / 448.0f;
}

// ---------------- quantize w: per 128x128 block scale ----------------
__global__ void quant_w_kernel(const float* __restrict__ w) {
    __shared__ float red[8];
    int nb = blockIdx.y, kc = blockIdx.x;
    int t = threadIdx.x;                 // 256 threads
    int lane = t & 31, wid = t >> 5;
    int rowInBlk = t >> 1;               // 0..127 (2 threads per row)
    int colOff = (t & 1) * 64;           // 0 or 64
    const float4* base = reinterpret_cast<const float4*>(
        w + (size_t)(nb * 128 + rowInBlk) * K_DIM + kc * 128 + colOff);

    float4 v[16];
    float amax = 0.0f;
    #pragma unroll
    for (int i = 0; i < 16; i++) {
        v[i] = base[i];
        amax = fmaxf(amax, fmaxf(fmaxf(fabsf(v[i].x), fabsf(v[i].y)),
                                 fmaxf(fabsf(v[i].z), fabsf(v[i].w))));
    }
    #pragma unroll
    for (int o = 16; o > 0; o >>= 1) amax = fmaxf(amax, __shfl_xor_sync(0xffffffffu, amax, o));
    if (lane == 0) red[wid] = amax;
    __syncthreads();
    if (t == 0) {
        float m = red[0];
        #pragma unroll
        for (int i = 1; i < 8; i++) m = fmaxf(m, red[i]);
        red[0] = fmaxf(m, 1e-4f);
    }
    __syncthreads();
    float s = red[0];
    float r = 448.0f / s;
    __nv_bfloat16* dst = g_wq + (size_t)(nb * 128 + rowInBlk) * K_DIM + kc * 128 + colOff;
    #pragma unroll
    for (int i = 0; i < 16; i++) {
        __nv_bfloat162 p0, p1;
        p0.x = fp8_rt(v[i].x, r); p0.y = fp8_rt(v[i].y, r);
        p1.x = fp8_rt(v[i].z, r); p1.y = fp8_rt(v[i].w, r);
        reinterpret_cast<__nv_bfloat162*>(dst + i * 4)[0] = p0;
        reinterpret_cast<__nv_bfloat162*>(dst + i * 4)[1] = p1;
    }
    if (t == 0) g_sw[nb * KCH + kc] = s / 448.0f;
}

// ---------------- GEMM: out = (xq @ wq^T) with per-128-chunk scale promotion ----------------
#define BM 128
#define BN 64
#define BK 32
#define ARS 80                    // A smem row stride bytes (64B data + 16 pad)
#define BRS 80
#define ABYTES (BM * ARS)         // 10240
#define BBYTES (BN * BRS)         // 5120
#define STAGE_BYTES (ABYTES + BBYTES)

__device__ __forceinline__ void cp_async16(uint32_t s, const void* g) {
    asm volatile("cp.async.cg.shared.global [%0], [%1], 16;\n" :: "r"(s), "l"(g));
}
__device__ __forceinline__ void mma16816(float* c, uint32_t a0, uint32_t a1, uint32_t a2,
                                         uint32_t a3, uint32_t b0, uint32_t b1) {
    asm volatile(
        "mma.sync.aligned.m16n8k16.row.col.f32.bf16.bf16.f32 "
        "{%0,%1,%2,%3}, {%4,%5,%6,%7}, {%8,%9}, {%0,%1,%2,%3};\n"
        : "+f"(c[0]), "+f"(c[1]), "+f"(c[2]), "+f"(c[3])
        : "r"(a0), "r"(a1), "r"(a2), "r"(a3), "r"(b0), "r"(b1));
}

// round through bf16 (reference output is bf16), store as fp32
__device__ __forceinline__ float bf16_round(float v) {
    return __bfloat162float(__float2bfloat16(v));
}

__global__ __launch_bounds__(256, 2) void gemm_kernel(float* __restrict__ out) {
    __shared__ __align__(16) unsigned char smem[2 * STAGE_BYTES];
    const int t = threadIdx.x;
    const int lane = t & 31, wid = t >> 5;
    const int gid = lane >> 2;            // groupID (0..7)
    const int tig = lane & 3;             // thread-in-group (0..3)
    const int warpM = wid >> 1, warpN = wid & 1;   // 4 x 2 warp grid, 32x32 warp tiles
    const int bm = blockIdx.y * BM, bn = blockIdx.x * BN;
    const int nb = bn >> 7;               // w-scale n-block
    const uint32_t sbase = (uint32_t)__cvta_generic_to_shared(smem);

    float accO[2][4][4];
    float accI[2][4][4];
    #pragma unroll
    for (int i = 0; i < 2; i++)
        #pragma unroll
        for (int j = 0; j < 4; j++)
            #pragma unroll
            for (int k = 0; k < 4; k++) { accO[i][j][k] = 0.0f; accI[i][j][k] = 0.0f; }

    // per-thread cp.async coordinates
    const int ar0 = t >> 2, ac0 = t & 3;
    const int ar1 = (t + 256) >> 2, ac1 = (t + 256) & 3;
    const int br = t >> 2, bc = t & 3;

    auto load_stage = [&](int kt, int stage) {
        uint32_t sA = sbase + stage * STAGE_BYTES;
        uint32_t sB = sA + ABYTES;
        int k0 = kt * BK;
        cp_async16(sA + ar0 * ARS + ac0 * 16, g_xq + (size_t)(bm + ar0) * K_DIM + k0 + ac0 * 8);
        cp_async16(sA + ar1 * ARS + ac1 * 16, g_xq + (size_t)(bm + ar1) * K_DIM + k0 + ac1 * 8);
        cp_async16(sB + br * BRS + bc * 16,   g_wq + (size_t)(bn + br) * K_DIM + k0 + bc * 8);
    };

    const int NKT = K_DIM / BK;  // 64
    load_stage(0, 0);
    asm volatile("cp.async.commit_group;\n");

    for (int kt = 0; kt < NKT; kt++) {
        int stage = kt & 1;
        asm volatile("cp.async.wait_group 0;\n");
        __syncthreads();
        if (kt + 1 < NKT) {
            load_stage(kt + 1, stage ^ 1);
            asm volatile("cp.async.commit_group;\n");
        }
        const char* cA = (const char*)smem + stage * STAGE_BYTES;
        const char* cB = cA + ABYTES;
        #pragma unroll
        for (int s = 0; s < 2; s++) {
            // explicit fragment loads per PTX mma.m16n8k16 tables
            uint32_t a[2][4];
            #pragma unroll
            for (int ma = 0; ma < 2; ma++) {
                int row = warpM * 32 + ma * 16 + gid;
                const char* p = cA + row * ARS + s * 32 + tig * 4;   // bytes
                a[ma][0] = *reinterpret_cast<const uint32_t*>(p);
                a[ma][1] = *reinterpret_cast<const uint32_t*>(p + 8 * ARS);
                a[ma][2] = *reinterpret_cast<const uint32_t*>(p + 16);
                a[ma][3] = *reinterpret_cast<const uint32_t*>(p + 8 * ARS + 16);
            }
            uint32_t b[4][2];
            #pragma unroll
            for (int na = 0; na < 4; na++) {
                int nrow = warpN * 32 + na * 8 + gid;
                const char* p = cB + nrow * BRS + s * 32 + tig * 4;
                b[na][0] = *reinterpret_cast<const uint32_t*>(p);
                b[na][1] = *reinterpret_cast<const uint32_t*>(p + 16);
            }
            #pragma unroll
            for (int ma = 0; ma < 2; ma++)
                #pragma unroll
                for (int na = 0; na < 4; na++)
                    mma16816(accI[ma][na], a[ma][0], a[ma][1], a[ma][2], a[ma][3],
                             b[na][0], b[na][1]);
        }
        if ((kt & 3) == 3) {  // end of a 128-K chunk: fold scales
            int chunk = kt >> 2;
            float swc = g_sw[nb * KCH + chunk];
            #pragma unroll
            for (int ma = 0; ma < 2; ma++) {
                int row0 = bm + warpM * 32 + ma * 16 + gid;
                float s0 = g_sx[row0 * KCH + chunk] * swc;
                float s1 = g_sx[(row0 + 8) * KCH + chunk] * swc;
                #pragma unroll
                for (int na = 0; na < 4; na++) {
                    accO[ma][na][0] += s0 * accI[ma][na][0];
                    accO[ma][na][1] += s0 * accI[ma][na][1];
                    accO[ma][na][2] += s1 * accI[ma][na][2];
                    accO[ma][na][3] += s1 * accI[ma][na][3];
                    accI[ma][na][0] = 0.0f; accI[ma][na][1] = 0.0f;
                    accI[ma][na][2] = 0.0f; accI[ma][na][3] = 0.0f;
                }
            }
        }
    }

    // epilogue: bf16-rounded values stored as FP32 (output buffer is float32)
    #pragma unroll
    for (int ma = 0; ma < 2; ma++) {
        int row0 = bm + warpM * 32 + ma * 16 + gid;
        #pragma unroll
        for (int na = 0; na < 4; na++) {
            int col = bn + warpN * 32 + na * 8 + tig * 2;
            float2 v0, v1;
            v0.x = bf16_round(accO[ma][na][0]);
            v0.y = bf16_round(accO[ma][na][1]);
            v1.x = bf16_round(accO[ma][na][2]);
            v1.y = bf16_round(accO[ma][na][3]);
            *reinterpret_cast<float2*>(out + (size_t)row0 * N_DIM + col) = v0;
            *reinterpret_cast<float2*>(out + (size_t)(row0 + 8) * N_DIM + col) = v1;
        }
    }
}

extern "C" void kernel_launch(void* const* d_in, const int* in_sizes, int n_in,
                              void* d_out, int out_size) {
    const float* x = (const float*)d_in[0];
    const float* w = (const float*)d_in[1];
    // robustness: identify operands by element count (x: M*K=16.7M, w: N*K=4.2M)
    if (n_in >= 2 && in_sizes[0] == N_DIM * K_DIM && in_sizes[1] > in_sizes[0]) {
        x = (const float*)d_in[1];
        w = (const float*)d_in[0];
    }
    float* out = (float*)d_out;
    (void)out_size;

    quant_x_kernel<<<M_DIM * KCH / 8, 256>>>(x);
    quant_w_kernel<<<dim3(KCH, NBLK), 256>>>(w);
    gemm_kernel<<<dim3(N_DIM / BN, M_DIM / BM), 256>>>(out);
}

// round 8
// speedup vs baseline: 1.1596x; 1.1596x over previous
#include <cuda_runtime.h>
#include <cuda_bf16.h>
#include <cuda_fp8.h>
#include <cstdint>

#define M_DIM 8192
#define N_DIM 2048
#define K_DIM 2048
#define KCH 16     // K / 128
#define NBLK 16    // N / 128

// ---------------- scratch (allocation-free: __device__ globals) ----------------
__device__ __align__(16) __nv_bfloat16 g_xq[(size_t)M_DIM * K_DIM];  // 32 MB
__device__ __align__(16) __nv_bfloat16 g_wq[(size_t)N_DIM * K_DIM];  //  8 MB
__device__ float g_sx[M_DIM * KCH];
__device__ float g_sw[NBLK * KCH];

// fp8 e4m3 round-trip on a float2 (RN, satfinite) -> exact bf16 pair
__device__ __forceinline__ __nv_bfloat162 fp8_rt2(float a, float b, float r) {
    float2 v = make_float2(a * r, b * r);
    __nv_fp8x2_storage_t q = __nv_cvt_float2_to_fp8x2(v, __NV_SATFINITE, __NV_E4M3);
    __half2_raw h = __nv_cvt_fp8x2_to_halfraw2(q, __NV_E4M3);
    float2 f = __half22float2(*reinterpret_cast<__half2*>(&h));
    return __floats2bfloat162_rn(f.x, f.y);   // e4m3 values are exact in bf16
}

// ---------------- quantize x: per (row, 128-chunk) scale ----------------
__global__ void quant_x_kernel(const float* __restrict__ x) {
    int wid = threadIdx.x >> 5, lane = threadIdx.x & 31;
    int id = blockIdx.x * 8 + wid;              // row-chunk id in [0, 8192*16)
    int row = id >> 4, c = id & 15;
    const float4* src = reinterpret_cast<const float4*>(x + (size_t)row * K_DIM + c * 128);
    float4 v = src[lane];
    float amax = fmaxf(fmaxf(fabsf(v.x), fabsf(v.y)), fmaxf(fabsf(v.z), fabsf(v.w)));
    #pragma unroll
    for (int o = 16; o > 0; o >>= 1) amax = fmaxf(amax, __shfl_xor_sync(0xffffffffu, amax, o));
    amax = fmaxf(amax, 1e-4f);
    float r = 448.0f / amax;
    __nv_bfloat162* dst =
        reinterpret_cast<__nv_bfloat162*>(g_xq + (size_t)row * K_DIM + c * 128 + lane * 4);
    dst[0] = fp8_rt2(v.x, v.y, r);
    dst[1] = fp8_rt2(v.z, v.w, r);
    if (lane == 0) g_sx[id] = amax / 448.0f;
}

// ---------------- quantize w: per 128x128 block scale ----------------
__global__ void quant_w_kernel(const float* __restrict__ w) {
    __shared__ float red[8];
    int nb = blockIdx.y, kc = blockIdx.x;
    int t = threadIdx.x;                 // 256 threads
    int lane = t & 31, wid = t >> 5;
    int rowInBlk = t >> 1;               // 0..127 (2 threads per row)
    int colOff = (t & 1) * 64;           // 0 or 64
    const float4* base = reinterpret_cast<const float4*>(
        w + (size_t)(nb * 128 + rowInBlk) * K_DIM + kc * 128 + colOff);

    float4 v[16];
    float amax = 0.0f;
    #pragma unroll
    for (int i = 0; i < 16; i++) {
        v[i] = base[i];
        amax = fmaxf(amax, fmaxf(fmaxf(fabsf(v[i].x), fabsf(v[i].y)),
                                 fmaxf(fabsf(v[i].z), fabsf(v[i].w))));
    }
    #pragma unroll
    for (int o = 16; o > 0; o >>= 1) amax = fmaxf(amax, __shfl_xor_sync(0xffffffffu, amax, o));
    if (lane == 0) red[wid] = amax;
    __syncthreads();
    if (t == 0) {
        float m = red[0];
        #pragma unroll
        for (int i = 1; i < 8; i++) m = fmaxf(m, red[i]);
        red[0] = fmaxf(m, 1e-4f);
    }
    __syncthreads();
    float s = red[0];
    float r = 448.0f / s;
    __nv_bfloat16* dst = g_wq + (size_t)(nb * 128 + rowInBlk) * K_DIM + kc * 128 + colOff;
    #pragma unroll
    for (int i = 0; i < 16; i++) {
        reinterpret_cast<__nv_bfloat162*>(dst + i * 4)[0] = fp8_rt2(v[i].x, v[i].y, r);
        reinterpret_cast<__nv_bfloat162*>(dst + i * 4)[1] = fp8_rt2(v[i].z, v[i].w, r);
    }
    if (t == 0) g_sw[nb * KCH + kc] = s / 448.0f;
}

// ---------------- GEMM: out = (xq @ wq^T) with per-128-chunk scale promotion ----------------
#define BM 128
#define BN 128
#define BK 32
#define ARS 80                    // smem row stride bytes (64B data + 16 pad)
#define ABYTES (BM * ARS)         // 10240
#define BBYTES (BN * ARS)         // 10240
#define STAGE_BYTES (ABYTES + BBYTES)   // 20480
#define NSTAGE 3

__device__ __forceinline__ void cp_async16(uint32_t s, const void* g) {
    asm volatile("cp.async.cg.shared.global [%0], [%1], 16;\n" :: "r"(s), "l"(g));
}
__device__ __forceinline__ void ldsm4(uint32_t& r0, uint32_t& r1, uint32_t& r2, uint32_t& r3,
                                      uint32_t addr) {
    asm volatile("ldmatrix.sync.aligned.m8n8.x4.shared.b16 {%0,%1,%2,%3}, [%4];\n"
                 : "=r"(r0), "=r"(r1), "=r"(r2), "=r"(r3) : "r"(addr));
}
__device__ __forceinline__ void mma16816(float* c, uint32_t a0, uint32_t a1, uint32_t a2,
                                         uint32_t a3, uint32_t b0, uint32_t b1) {
    asm volatile(
        "mma.sync.aligned.m16n8k16.row.col.f32.bf16.bf16.f32 "
        "{%0,%1,%2,%3}, {%4,%5,%6,%7}, {%8,%9}, {%0,%1,%2,%3};\n"
        : "+f"(c[0]), "+f"(c[1]), "+f"(c[2]), "+f"(c[3])
        : "r"(a0), "r"(a1), "r"(a2), "r"(a3), "r"(b0), "r"(b1));
}
__device__ __forceinline__ float bf16_round(float v) {
    return __bfloat162float(__float2bfloat16(v));
}

__global__ __launch_bounds__(256, 1) void gemm_kernel(float* __restrict__ out) {
    extern __shared__ __align__(16) unsigned char smem[];
    const int t = threadIdx.x;
    const int lane = t & 31, wid = t >> 5;
    const int gid = lane >> 2;            // groupID (0..7)
    const int tig = lane & 3;             // thread-in-group (0..3)
    const int warpM = wid >> 1, warpN = wid & 1;   // 4 x 2 warp grid, 32x64 warp tiles
    const int bm = blockIdx.y * BM, bn = blockIdx.x * BN;
    const int nb = bn >> 7;               // w-scale n-block
    const uint32_t sbase = (uint32_t)__cvta_generic_to_shared(smem);

    float accO[2][8][4];
    float accI[2][8][4];
    #pragma unroll
    for (int i = 0; i < 2; i++)
        #pragma unroll
        for (int j = 0; j < 8; j++)
            #pragma unroll
            for (int k = 0; k < 4; k++) { accO[i][j][k] = 0.0f; accI[i][j][k] = 0.0f; }

    // per-thread cp.async coordinates: 512 16B-chunks per operand, 2 per thread
    const int r0 = t >> 2, c0 = t & 3;
    const int r1 = (t + 256) >> 2, c1 = (t + 256) & 3;

    auto load_stage = [&](int kt, int stage) {
        uint32_t sA = sbase + stage * STAGE_BYTES;
        uint32_t sB = sA + ABYTES;
        int k0 = kt * BK;
        cp_async16(sA + r0 * ARS + c0 * 16, g_xq + (size_t)(bm + r0) * K_DIM + k0 + c0 * 8);
        cp_async16(sA + r1 * ARS + c1 * 16, g_xq + (size_t)(bm + r1) * K_DIM + k0 + c1 * 8);
        cp_async16(sB + r0 * ARS + c0 * 16, g_wq + (size_t)(bn + r0) * K_DIM + k0 + c0 * 8);
        cp_async16(sB + r1 * ARS + c1 * 16, g_wq + (size_t)(bn + r1) * K_DIM + k0 + c1 * 8);
    };

    const int NKT = K_DIM / BK;  // 64
    load_stage(0, 0);
    asm volatile("cp.async.commit_group;\n");
    load_stage(1, 1);
    asm volatile("cp.async.commit_group;\n");

    for (int kt = 0; kt < NKT; kt++) {
        int stage = kt % NSTAGE;
        asm volatile("cp.async.wait_group 1;\n");
        __syncthreads();
        if (kt + 2 < NKT) {
            load_stage(kt + 2, (kt + 2) % NSTAGE);
            asm volatile("cp.async.commit_group;\n");
        }
        uint32_t sA = sbase + stage * STAGE_BYTES;
        uint32_t sB = sA + ABYTES;
        #pragma unroll
        for (int s = 0; s < 2; s++) {
            // A fragments via ldmatrix (mapping verified: identical results to explicit loads)
            uint32_t a[2][4];
            #pragma unroll
            for (int ma = 0; ma < 2; ma++) {
                int row = warpM * 32 + ma * 16 + (lane & 15);
                uint32_t addr = sA + row * ARS + (2 * s + (lane >> 4)) * 16;
                ldsm4(a[ma][0], a[ma][1], a[ma][2], a[ma][3], addr);
            }
            // B fragments
            uint32_t b[4][4];
            #pragma unroll
            for (int g = 0; g < 4; g++) {
                int nrow = warpN * 64 + g * 16 + (((lane >> 4) & 1) << 3) + (lane & 7);
                int cch = 2 * s + ((lane >> 3) & 1);
                uint32_t addr = sB + nrow * ARS + cch * 16;
                ldsm4(b[g][0], b[g][1], b[g][2], b[g][3], addr);
            }
            #pragma unroll
            for (int ma = 0; ma < 2; ma++)
                #pragma unroll
                for (int na = 0; na < 8; na++)
                    mma16816(accI[ma][na], a[ma][0], a[ma][1], a[ma][2], a[ma][3],
                             b[na >> 1][(na & 1) * 2 + 0], b[na >> 1][(na & 1) * 2 + 1]);
        }
        if ((kt & 3) == 3) {  // end of a 128-K chunk: fold scales
            int chunk = kt >> 2;
            float swc = g_sw[nb * KCH + chunk];
            #pragma unroll
            for (int ma = 0; ma < 2; ma++) {
                int row0 = bm + warpM * 32 + ma * 16 + gid;
                float s0 = g_sx[row0 * KCH + chunk] * swc;
                float s1 = g_sx[(row0 + 8) * KCH + chunk] * swc;
                #pragma unroll
                for (int na = 0; na < 8; na++) {
                    accO[ma][na][0] += s0 * accI[ma][na][0];
                    accO[ma][na][1] += s0 * accI[ma][na][1];
                    accO[ma][na][2] += s1 * accI[ma][na][2];
                    accO[ma][na][3] += s1 * accI[ma][na][3];
                    accI[ma][na][0] = 0.0f; accI[ma][na][1] = 0.0f;
                    accI[ma][na][2] = 0.0f; accI[ma][na][3] = 0.0f;
                }
            }
        }
    }

    // epilogue: bf16-rounded values stored as FP32 (output buffer is float32)
    #pragma unroll
    for (int ma = 0; ma < 2; ma++) {
        int row0 = bm + warpM * 32 + ma * 16 + gid;
        #pragma unroll
        for (int na = 0; na < 8; na++) {
            int col = bn + warpN * 64 + na * 8 + tig * 2;
            float2 v0, v1;
            v0.x = bf16_round(accO[ma][na][0]);
            v0.y = bf16_round(accO[ma][na][1]);
            v1.x = bf16_round(accO[ma][na][2]);
            v1.y = bf16_round(accO[ma][na][3]);
            *reinterpret_cast<float2*>(out + (size_t)row0 * N_DIM + col) = v0;
            *reinterpret_cast<float2*>(out + (size_t)(row0 + 8) * N_DIM + col) = v1;
        }
    }
}

extern "C" void kernel_launch(void* const* d_in, const int* in_sizes, int n_in,
                              void* d_out, int out_size) {
    const float* x = (const float*)d_in[0];
    const float* w = (const float*)d_in[1];
    // robustness: identify operands by element count (x: M*K=16.7M, w: N*K=4.2M)
    if (n_in >= 2 && in_sizes[0] == N_DIM * K_DIM && in_sizes[1] > in_sizes[0]) {
        x = (const float*)d_in[1];
        w = (const float*)d_in[0];
    }
    float* out = (float*)d_out;
    (void)out_size;

    static bool attr_set = false;
    if (!attr_set) {
        cudaFuncSetAttribute(gemm_kernel, cudaFuncAttributeMaxDynamicSharedMemorySize,
                             NSTAGE * STAGE_BYTES);
        attr_set = true;
    }

    quant_x_kernel<<<M_DIM * KCH / 8, 256>>>(x);
    quant_w_kernel<<<dim3(KCH, NBLK), 256>>>(w);
    gemm_kernel<<<dim3(N_DIM / BN, M_DIM / BM), 256, NSTAGE * STAGE_BYTES>>>(out);
}

// round 12
// speedup vs baseline: 1.3167x; 1.1355x over previous
#include <cuda_runtime.h>
#include <cuda_bf16.h>
#include <cuda_fp8.h>
#include <cstdint>

#define M_DIM 8192
#define N_DIM 2048
#define K_DIM 2048
#define KCH 16     // K / 128
#define NBLK 16    // N / 128

// ---------------- scratch (allocation-free: __device__ globals) ----------------
// q-values stored as raw e4m3 bytes (exact); scales separate for fp32 promotion.
__device__ __align__(16) uint8_t g_xq[(size_t)M_DIM * K_DIM];  // 16 MB
__device__ __align__(16) uint8_t g_wq[(size_t)N_DIM * K_DIM];  //  4 MB
__device__ float g_sx[M_DIM * KCH];
__device__ float g_sw[NBLK * KCH];

// pack 4 floats -> 4 e4m3 bytes (RN, satfinite)
__device__ __forceinline__ uint32_t fp8x4(float a, float b, float c, float d, float r) {
    __nv_fp8x2_storage_t q01 =
        __nv_cvt_float2_to_fp8x2(make_float2(a * r, b * r), __NV_SATFINITE, __NV_E4M3);
    __nv_fp8x2_storage_t q23 =
        __nv_cvt_float2_to_fp8x2(make_float2(c * r, d * r), __NV_SATFINITE, __NV_E4M3);
    return (uint32_t)q01 | ((uint32_t)q23 << 16);
}

// ---------------- quantize x: per (row, 128-chunk) scale ----------------
__global__ void quant_x_kernel(const float* __restrict__ x) {
    int wid = threadIdx.x >> 5, lane = threadIdx.x & 31;
    int id = blockIdx.x * 8 + wid;              // row-chunk id
    int row = id >> 4, c = id & 15;
    const float4* src = reinterpret_cast<const float4*>(x + (size_t)row * K_DIM + c * 128);
    float4 v = src[lane];
    float amax = fmaxf(fmaxf(fabsf(v.x), fabsf(v.y)), fmaxf(fabsf(v.z), fabsf(v.w)));
    #pragma unroll
    for (int o = 16; o > 0; o >>= 1) amax = fmaxf(amax, __shfl_xor_sync(0xffffffffu, amax, o));
    amax = fmaxf(amax, 1e-4f);
    float r = 448.0f / amax;
    *reinterpret_cast<uint32_t*>(g_xq + (size_t)row * K_DIM + c * 128 + lane * 4) =
        fp8x4(v.x, v.y, v.z, v.w, r);
    if (lane == 0) g_sx[id] = amax / 448.0f;
}

// ---------------- quantize w: per 128x128 block scale ----------------
__global__ void quant_w_kernel(const float* __restrict__ w) {
    __shared__ float red[8];
    int nb = blockIdx.y, kc = blockIdx.x;
    int t = threadIdx.x;
    int lane = t & 31, wid = t >> 5;
    int rowInBlk = t >> 1;
    int colOff = (t & 1) * 64;
    const float4* base = reinterpret_cast<const float4*>(
        w + (size_t)(nb * 128 + rowInBlk) * K_DIM + kc * 128 + colOff);
    float4 v[16];
    float amax = 0.0f;
    #pragma unroll
    for (int i = 0; i < 16; i++) {
        v[i] = base[i];
        amax = fmaxf(amax, fmaxf(fmaxf(fabsf(v[i].x), fabsf(v[i].y)),
                                 fmaxf(fabsf(v[i].z), fabsf(v[i].w))));
    }
    #pragma unroll
    for (int o = 16; o > 0; o >>= 1) amax = fmaxf(amax, __shfl_xor_sync(0xffffffffu, amax, o));
    if (lane == 0) red[wid] = amax;
    __syncthreads();
    if (t == 0) {
        float m = red[0];
        #pragma unroll
        for (int i = 1; i < 8; i++) m = fmaxf(m, red[i]);
        red[0] = fmaxf(m, 1e-4f);
    }
    __syncthreads();
    float s = red[0];
    float r = 448.0f / s;
    uint8_t* dst = g_wq + (size_t)(nb * 128 + rowInBlk) * K_DIM + kc * 128 + colOff;
    #pragma unroll
    for (int i = 0; i < 16; i++)
        *reinterpret_cast<uint32_t*>(dst + i * 4) = fp8x4(v[i].x, v[i].y, v[i].z, v[i].w, r);
    if (t == 0) g_sw[nb * KCH + kc] = s / 448.0f;
}

// ------- GEMM: fp8 QMMA (m16n8k32) with exact fp32 per-128-chunk scale promotion -------
#define BM 128
#define BN 128
#define BK 64                     // fp8 elements per k-tile (= 64 bytes per row)
#define ARS 80                    // smem row stride bytes (64B data + 16 pad)
#define ABYTES (BM * ARS)         // 10240
#define BBYTES (BN * ARS)         // 10240
#define STAGE_BYTES (ABYTES + BBYTES)   // 20480
#define NSTAGE 3

__device__ __forceinline__ void cp_async16(uint32_t s, const void* g) {
    asm volatile("cp.async.cg.shared.global [%0], [%1], 16;\n" :: "r"(s), "l"(g));
}
__device__ __forceinline__ void ldsm4(uint32_t& r0, uint32_t& r1, uint32_t& r2, uint32_t& r3,
                                      uint32_t addr) {
    asm volatile("ldmatrix.sync.aligned.m8n8.x4.shared.b16 {%0,%1,%2,%3}, [%4];\n"
                 : "=r"(r0), "=r"(r1), "=r"(r2), "=r"(r3) : "r"(addr));
}
// fp8 e4m3 QMMA, fp32 accum: A 16x32 (4 regs), B 32x8 (2 regs)
__device__ __forceinline__ void qmma(float* c, uint32_t a0, uint32_t a1, uint32_t a2,
                                     uint32_t a3, uint32_t b0, uint32_t b1) {
    asm volatile(
        "mma.sync.aligned.m16n8k32.row.col.f32.e4m3.e4m3.f32 "
        "{%0,%1,%2,%3}, {%4,%5,%6,%7}, {%8,%9}, {%0,%1,%2,%3};\n"
        : "+f"(c[0]), "+f"(c[1]), "+f"(c[2]), "+f"(c[3])
        : "r"(a0), "r"(a1), "r"(a2), "r"(a3), "r"(b0), "r"(b1));
}
__device__ __forceinline__ float bf16_round(float v) {
    return __bfloat162float(__float2bfloat16(v));
}

__global__ __launch_bounds__(256, 1) void gemm_kernel(float* __restrict__ out) {
    extern __shared__ __align__(16) unsigned char smem[];
    const int t = threadIdx.x;
    const int lane = t & 31, wid = t >> 5;
    const int gid = lane >> 2;            // groupID (0..7)
    const int tig = lane & 3;             // thread-in-group (0..3)
    const int warpM = wid >> 1, warpN = wid & 1;   // 4 x 2 warp grid, 32x64 warp tiles
    const int bm = blockIdx.y * BM, bn = blockIdx.x * BN;
    const int nb = bn >> 7;
    const uint32_t sbase = (uint32_t)__cvta_generic_to_shared(smem);

    float accO[2][8][4];
    float accI[2][8][4];
    #pragma unroll
    for (int i = 0; i < 2; i++)
        #pragma unroll
        for (int j = 0; j < 8; j++)
            #pragma unroll
            for (int k = 0; k < 4; k++) { accO[i][j][k] = 0.0f; accI[i][j][k] = 0.0f; }

    // cp.async coordinates: 128 rows x 4 16B-chunks per operand = 512 chunks, 2/thread
    const int r0 = t >> 2, c0 = t & 3;
    const int r1 = (t + 256) >> 2, c1 = (t + 256) & 3;

    auto load_stage = [&](int kt, int stage) {
        uint32_t sA = sbase + stage * STAGE_BYTES;
        uint32_t sB = sA + ABYTES;
        int k0 = kt * BK;
        cp_async16(sA + r0 * ARS + c0 * 16, g_xq + (size_t)(bm + r0) * K_DIM + k0 + c0 * 16);
        cp_async16(sA + r1 * ARS + c1 * 16, g_xq + (size_t)(bm + r1) * K_DIM + k0 + c1 * 16);
        cp_async16(sB + r0 * ARS + c0 * 16, g_wq + (size_t)(bn + r0) * K_DIM + k0 + c0 * 16);
        cp_async16(sB + r1 * ARS + c1 * 16, g_wq + (size_t)(bn + r1) * K_DIM + k0 + c1 * 16);
    };

    const int NKT = K_DIM / BK;  // 32
    load_stage(0, 0);
    asm volatile("cp.async.commit_group;\n");
    load_stage(1, 1);
    asm volatile("cp.async.commit_group;\n");

    for (int kt = 0; kt < NKT; kt++) {
        int stage = kt % NSTAGE;
        asm volatile("cp.async.wait_group 1;\n");
        __syncthreads();
        if (kt + 2 < NKT) {
            load_stage(kt + 2, (kt + 2) % NSTAGE);
            asm volatile("cp.async.commit_group;\n");
        }
        uint32_t sA = sbase + stage * STAGE_BYTES;
        uint32_t sB = sA + ABYTES;
        #pragma unroll
        for (int s = 0; s < 2; s++) {        // two k32 steps per 64B tile
            // A fragments: same byte addresses as verified bf16 scheme
            uint32_t a[2][4];
            #pragma unroll
            for (int ma = 0; ma < 2; ma++) {
                int row = warpM * 32 + ma * 16 + (lane & 15);
                uint32_t addr = sA + row * ARS + (2 * s + (lane >> 4)) * 16;
                ldsm4(a[ma][0], a[ma][1], a[ma][2], a[ma][3], addr);
            }
            // B fragments
            uint32_t b[4][4];
            #pragma unroll
            for (int g = 0; g < 4; g++) {
                int nrow = warpN * 64 + g * 16 + (((lane >> 4) & 1) << 3) + (lane & 7);
                int cch = 2 * s + ((lane >> 3) & 1);
                uint32_t addr = sB + nrow * ARS + cch * 16;
                ldsm4(b[g][0], b[g][1], b[g][2], b[g][3], addr);
            }
            #pragma unroll
            for (int ma = 0; ma < 2; ma++)
                #pragma unroll
                for (int na = 0; na < 8; na++)
                    qmma(accI[ma][na], a[ma][0], a[ma][1], a[ma][2], a[ma][3],
                         b[na >> 1][(na & 1) * 2 + 0], b[na >> 1][(na & 1) * 2 + 1]);
        }
        if (kt & 1) {  // end of a 128-K chunk (2 k-tiles): fold scales exactly
            int chunk = kt >> 1;
            float swc = g_sw[nb * KCH + chunk];
            #pragma unroll
            for (int ma = 0; ma < 2; ma++) {
                int row0 = bm + warpM * 32 + ma * 16 + gid;
                float s0 = g_sx[row0 * KCH + chunk] * swc;
                float s1 = g_sx[(row0 + 8) * KCH + chunk] * swc;
                #pragma unroll
                for (int na = 0; na < 8; na++) {
                    accO[ma][na][0] += s0 * accI[ma][na][0];
                    accO[ma][na][1] += s0 * accI[ma][na][1];
                    accO[ma][na][2] += s1 * accI[ma][na][2];
                    accO[ma][na][3] += s1 * accI[ma][na][3];
                    accI[ma][na][0] = 0.0f; accI[ma][na][1] = 0.0f;
                    accI[ma][na][2] = 0.0f; accI[ma][na][3] = 0.0f;
                }
            }
        }
    }

    // epilogue: bf16-rounded values stored as FP32 (output buffer is float32)
    #pragma unroll
    for (int ma = 0; ma < 2; ma++) {
        int row0 = bm + warpM * 32 + ma * 16 + gid;
        #pragma unroll
        for (int na = 0; na < 8; na++) {
            int col = bn + warpN * 64 + na * 8 + tig * 2;
            float2 v0, v1;
            v0.x = bf16_round(accO[ma][na][0]);
            v0.y = bf16_round(accO[ma][na][1]);
            v1.x = bf16_round(accO[ma][na][2]);
            v1.y = bf16_round(accO[ma][na][3]);
            *reinterpret_cast<float2*>(out + (size_t)row0 * N_DIM + col) = v0;
            *reinterpret_cast<float2*>(out + (size_t)(row0 + 8) * N_DIM + col) = v1;
        }
    }
}

extern "C" void kernel_launch(void* const* d_in, const int* in_sizes, int n_in,
                              void* d_out, int out_size) {
    const float* x = (const float*)d_in[0];
    const float* w = (const float*)d_in[1];
    if (n_in >= 2 && in_sizes[0] == N_DIM * K_DIM && in_sizes[1] > in_sizes[0]) {
        x = (const float*)d_in[1];
        w = (const float*)d_in[0];
    }
    float* out = (float*)d_out;
    (void)out_size;

    static bool attr_set = false;
    if (!attr_set) {
        cudaFuncSetAttribute(gemm_kernel, cudaFuncAttributeMaxDynamicSharedMemorySize,
                             NSTAGE * STAGE_BYTES);
        attr_set = true;
    }

    quant_x_kernel<<<M_DIM * KCH / 8, 256>>>(x);
    quant_w_kernel<<<dim3(KCH, NBLK), 256>>>(w);
    gemm_kernel<<<dim3(N_DIM / BN, M_DIM / BM), 256, NSTAGE * STAGE_BYTES>>>(out);
}